// round 16
// baseline (speedup 1.0000x reference)
#include <cuda_runtime.h>
#include <cuda_fp16.h>
#include <math.h>
#include <stdint.h>

#define CC 128
#define NMAX 300000
#define NWORDS (1u<<20)
#define STRIDE_Bc 4194304
#define STRIDE_Tc 262144
#define STRIDE_Hc 512

// ================= device scratch =================
__device__ uint32_t g_X2h[(size_t)NMAX*64];   // packed half2, [row][64]
__device__ unsigned g_bitmap[NWORDS];
__device__ unsigned g_dup[NWORDS];
__device__ unsigned g_wordscan[NWORDS];
__device__ unsigned g_blocksum[1024];
__device__ unsigned g_blockoff[1024];
__device__ unsigned g_U;
__device__ unsigned g_ndup;
__device__ unsigned g_duplist[NMAX];
__device__ float    g_colsum[CC];
__device__ float    g_scale[CC];

// ================= helpers =================
__device__ __forceinline__ uint32_t smem_u32(const void* p){
    uint32_t a;
    asm("{ .reg .u64 t; cvta.to.shared.u64 t, %1; cvt.u32.u64 %0, t; }" : "=r"(a) : "l"(p));
    return a;
}

__device__ __forceinline__ void ldsm_x4(uint32_t addr, uint32_t& r0, uint32_t& r1,
                                        uint32_t& r2, uint32_t& r3){
    asm volatile("ldmatrix.sync.aligned.m8n8.x4.shared.b16 {%0,%1,%2,%3}, [%4];"
        : "=r"(r0),"=r"(r1),"=r"(r2),"=r"(r3) : "r"(addr));
}

__device__ __forceinline__ void mma_f16(float* d, const uint32_t* a, uint32_t b0, uint32_t b1){
    asm volatile("mma.sync.aligned.m16n8k16.row.col.f32.f16.f16.f32 "
        "{%0,%1,%2,%3}, {%4,%5,%6,%7}, {%8,%9}, {%0,%1,%2,%3};"
        : "+f"(d[0]),"+f"(d[1]),"+f"(d[2]),"+f"(d[3])
        : "r"(a[0]),"r"(a[1]),"r"(a[2]),"r"(a[3]), "r"(b0),"r"(b1));
}

__device__ __forceinline__ uint32_t packh2(float a, float b){
    __half2 h = __floats2half2_rn(a, b);
    return *reinterpret_cast<uint32_t*>(&h);
}
__device__ __forceinline__ float2 unpackh2(uint32_t u){
    __half2 h = *reinterpret_cast<__half2*>(&u);
    return __half22float2(h);
}

__device__ __forceinline__ void cp_async16(uint32_t dst, const void* src, int src_bytes){
    asm volatile("cp.async.cg.shared.global [%0], [%1], 16, %2;"
        :: "r"(dst), "l"(src), "r"(src_bytes) : "memory");
}
#define CP_COMMIT() asm volatile("cp.async.commit_group;" ::: "memory")
#define CP_WAIT_ALL() asm volatile("cp.async.wait_group 0;" ::: "memory")

// streaming 16B store (evict-first; write-once outputs)
__device__ __forceinline__ void stcs4(float* p, float4 v){
    asm volatile("st.global.cs.v4.f32 [%0], {%1,%2,%3,%4};"
        :: "l"(p), "f"(v.x), "f"(v.y), "f"(v.z), "f"(v.w) : "memory");
}

// ---------------- fused-kernel SMEM layout (bytes) ----------------
#define SW        136          // W panel row stride (fp16 elements)
#define AW        68           // sA row stride (uint32 words = half2 pairs)
#define RAWSTRIDE 528          // raw fp32 row stride (132 floats, 16B aligned)
#define OFF_W1H   0
#define OFF_W2H   34816
#define OFF_SA    69632
#define OFF_RAW   104448       // 128 * 528 = 67584
#define OFF_G1    172032
#define OFF_B1    172544
#define OFF_G2    173056
#define OFF_B2    173568
#define OFF_LN    174080       // float2[128][2]
#define SMEM_FUSED 176128

// 1-pass fp16 GEMM over the staged A tile: acc[8][4] = 16 rows x 64 cols (this warp)
__device__ __forceinline__ void do_gemm(float (&acc)[8][4],
                                        const uint32_t* __restrict__ sA,
                                        uint32_t wbh,
                                        int arow0, int chalf, int belem, int rq, int q)
{
    #pragma unroll
    for (int ks = 0; ks < 8; ks++){
        uint32_t ah[4];
        const int wi0 = (arow0 + rq) * AW + ks*8 + q;
        const int wi1 = wi0 + 8*AW;
        ah[0] = sA[wi0];   ah[1] = sA[wi1];
        ah[2] = sA[wi0+4]; ah[3] = sA[wi1+4];
        #pragma unroll
        for (int np = 0; np < 4; np++){
            uint32_t boff = (uint32_t)(((chalf*64 + np*16)*SW + ks*16 + belem) * 2);
            uint32_t b0,b1,b2,b3;
            ldsm_x4(wbh + boff, b0,b1,b2,b3);
            mma_f16(acc[np*2],   ah, b0, b1);
            mma_f16(acc[np*2+1], ah, b2, b3);
        }
    }
}

// ================= fused GEMM1->LN1->ReLU->GEMM2->LN2 (cp.async pipelined) =================
__global__ __launch_bounds__(512, 1)
void fused_kernel(const float* __restrict__ A,
                  const float* __restrict__ W1, const float* __restrict__ g1v, const float* __restrict__ b1v,
                  const float* __restrict__ W2, const float* __restrict__ g2v, const float* __restrict__ b2v,
                  uint32_t* __restrict__ X2h, int Nrows)
{
    extern __shared__ char smem[];
    uint32_t sb = smem_u32(smem);
    uint32_t* sA = (uint32_t*)(smem + OFF_SA);
    float* sG1 = (float*)(smem + OFF_G1);
    float* sB1 = (float*)(smem + OFF_B1);
    float* sG2 = (float*)(smem + OFF_G2);
    float* sB2 = (float*)(smem + OFF_B2);
    float2* sLN = (float2*)(smem + OFF_LN);

    const int tid = threadIdx.x, lane = tid & 31, wid = tid >> 5;
    const int q = lane & 3, rq = lane >> 2;
    const int g = wid >> 1, chalf = wid & 1;
    const int jj = lane >> 3, rr = lane & 7;
    const int belem = ((jj >= 2 ? 8 : 0) + rr) * SW + ((jj & 1) ? 8 : 0);
    const int arow0 = g * 16;

    const int srow = tid >> 2, scolg = tid & 3;
    const uint32_t rawdst = sb + OFF_RAW + (uint32_t)(srow*RAWSTRIDE + scolg*128);
    const float* sRawRd = (const float*)(smem + OFF_RAW) + srow*132 + scolg*32;
    uint32_t* sAwr = sA + srow*AW + scolg*16;

    // ---- load W1/W2 fp16 panels ----
    {
        int n = tid & 127, kq = tid >> 7;
        __half* w1h = (__half*)(smem + OFF_W1H);
        __half* w2h = (__half*)(smem + OFF_W2H);
        #pragma unroll 4
        for (int k = kq*32; k < kq*32 + 32; k++){
            w1h[n*SW + k] = __float2half_rn(W1[k*CC + n]);
            w2h[n*SW + k] = __float2half_rn(W2[k*CC + n]);
        }
        if (tid < CC){ sG1[tid] = g1v[tid]; sB1[tid] = b1v[tid]; sG2[tid] = g2v[tid]; sB2[tid] = b2v[tid]; }
    }

    const uint32_t wb1h = sb + OFF_W1H;
    const uint32_t wb2h = sb + OFF_W2H;

    float csum[16];
    #pragma unroll
    for (int j = 0; j < 16; j++) csum[j] = 0.f;

    const int NT = (Nrows + 127) >> 7;
    const int G = gridDim.x;

    // prologue: prefetch first owned tile's raw fp32
    if (blockIdx.x < NT){
        int grow = blockIdx.x*128 + srow;
        int ok16 = (grow < Nrows) ? 16 : 0;
        const float* src = A + (size_t)grow*CC + scolg*32;
        #pragma unroll
        for (int j = 0; j < 8; j++)
            cp_async16(rawdst + j*16, src + j*4, ok16);
    }
    CP_COMMIT();
    __syncthreads();   // W panels visible

    for (int tile = blockIdx.x; tile < NT; tile += G){
        // ---- 1. wait raw tile, convert fp32->fp16 into sA ----
        CP_WAIT_ALL();
        __syncthreads();
        {
            #pragma unroll
            for (int j = 0; j < 8; j++){
                float4 v = *(const float4*)(sRawRd + j*4);
                sAwr[j*2]   = packh2(v.x, v.y);
                sAwr[j*2+1] = packh2(v.z, v.w);
            }
        }
        __syncthreads();

        // ---- 1b. prefetch next tile's raw (flies under compute) ----
        int tnext = tile + G;
        if (tnext < NT){
            int grow = tnext*128 + srow;
            int ok16 = (grow < Nrows) ? 16 : 0;
            const float* src = A + (size_t)grow*CC + scolg*32;
            #pragma unroll
            for (int j = 0; j < 8; j++)
                cp_async16(rawdst + j*16, src + j*4, ok16);
        }
        CP_COMMIT();

        const int r0 = tile*128 + g*16 + rq;
        const bool ok0 = r0 < Nrows, ok1 = (r0 + 8) < Nrows;

        // ---- 2. GEMM1 ----
        float acc[8][4];
        #pragma unroll
        for (int t = 0; t < 8; t++)
            #pragma unroll
            for (int j = 0; j < 4; j++) acc[t][j] = 0.f;
        do_gemm(acc, sA, wb1h, arow0, chalf, belem, rq, q);

        // ---- 3. LN1 stats + cross-pair exchange ----
        float s0=0.f, q0=0.f, s1=0.f, q1=0.f;
        #pragma unroll
        for (int t = 0; t < 8; t++){
            s0 += acc[t][0] + acc[t][1];
            q0 += acc[t][0]*acc[t][0] + acc[t][1]*acc[t][1];
            s1 += acc[t][2] + acc[t][3];
            q1 += acc[t][2]*acc[t][2] + acc[t][3]*acc[t][3];
        }
        #pragma unroll
        for (int o = 1; o <= 2; o <<= 1){
            s0 += __shfl_xor_sync(0xffffffffu, s0, o);
            q0 += __shfl_xor_sync(0xffffffffu, q0, o);
            s1 += __shfl_xor_sync(0xffffffffu, s1, o);
            q1 += __shfl_xor_sync(0xffffffffu, q1, o);
        }
        if (q == 0){
            sLN[(arow0 + rq)*2 + chalf]     = make_float2(s0, q0);
            sLN[(arow0 + rq + 8)*2 + chalf] = make_float2(s1, q1);
        }
        __syncthreads();
        {
            float2 p0 = sLN[(arow0 + rq)*2 + (chalf^1)];
            float2 p1 = sLN[(arow0 + rq + 8)*2 + (chalf^1)];
            float S0 = s0 + p0.x, Q0 = q0 + p0.y;
            float S1 = s1 + p1.x, Q1 = q1 + p1.y;
            float mu0 = S0*(1.f/128.f), mu1 = S1*(1.f/128.f);
            float rs0 = rsqrtf(Q0*(1.f/128.f) - mu0*mu0 + 1e-5f);
            float rs1 = rsqrtf(Q1*(1.f/128.f) - mu1*mu1 + 1e-5f);
            // ---- 4. LN1 apply + ReLU -> fp16 Y into sA ----
            #pragma unroll
            for (int t = 0; t < 8; t++){
                int c = chalf*64 + t*8 + 2*q;
                float ga = sG1[c], gb = sG1[c+1], ba = sB1[c], bb = sB1[c+1];
                float y0 = fmaxf((acc[t][0]-mu0)*rs0*ga + ba, 0.f);
                float y1 = fmaxf((acc[t][1]-mu0)*rs0*gb + bb, 0.f);
                float y2 = fmaxf((acc[t][2]-mu1)*rs1*ga + ba, 0.f);
                float y3 = fmaxf((acc[t][3]-mu1)*rs1*gb + bb, 0.f);
                int w0 = (arow0 + rq)*AW + chalf*32 + t*4 + q;
                int w1 = w0 + 8*AW;
                sA[w0] = packh2(y0, y1);
                sA[w1] = packh2(y2, y3);
            }
        }
        __syncthreads();   // Y visible

        // ---- 5. GEMM2 ----
        #pragma unroll
        for (int t = 0; t < 8; t++)
            #pragma unroll
            for (int j = 0; j < 4; j++) acc[t][j] = 0.f;
        do_gemm(acc, sA, wb2h, arow0, chalf, belem, rq, q);

        // ---- 6. LN2 stats + exchange ----
        s0=0.f; q0=0.f; s1=0.f; q1=0.f;
        #pragma unroll
        for (int t = 0; t < 8; t++){
            s0 += acc[t][0] + acc[t][1];
            q0 += acc[t][0]*acc[t][0] + acc[t][1]*acc[t][1];
            s1 += acc[t][2] + acc[t][3];
            q1 += acc[t][2]*acc[t][2] + acc[t][3]*acc[t][3];
        }
        #pragma unroll
        for (int o = 1; o <= 2; o <<= 1){
            s0 += __shfl_xor_sync(0xffffffffu, s0, o);
            q0 += __shfl_xor_sync(0xffffffffu, q0, o);
            s1 += __shfl_xor_sync(0xffffffffu, s1, o);
            q1 += __shfl_xor_sync(0xffffffffu, q1, o);
        }
        if (q == 0){
            sLN[(arow0 + rq)*2 + chalf]     = make_float2(s0, q0);
            sLN[(arow0 + rq + 8)*2 + chalf] = make_float2(s1, q1);
        }
        __syncthreads();   // all GEMM2 sA reads done -> restage safe next iter
        {
            float2 p0 = sLN[(arow0 + rq)*2 + (chalf^1)];
            float2 p1 = sLN[(arow0 + rq + 8)*2 + (chalf^1)];
            float S0 = s0 + p0.x, Q0 = q0 + p0.y;
            float S1 = s1 + p1.x, Q1 = q1 + p1.y;
            float mu0 = S0*(1.f/128.f), mu1 = S1*(1.f/128.f);
            float rs0 = rsqrtf(Q0*(1.f/128.f) - mu0*mu0 + 1e-5f);
            float rs1 = rsqrtf(Q1*(1.f/128.f) - mu1*mu1 + 1e-5f);
            uint32_t* px0 = X2h + (size_t)r0*64;
            uint32_t* px1 = px0 + 8*64;
            #pragma unroll
            for (int t = 0; t < 8; t++){
                int c = chalf*64 + t*8 + 2*q;
                int widx = chalf*32 + t*4 + q;
                float ga = sG2[c], gb = sG2[c+1], ba = sB2[c], bb = sB2[c+1];
                if (ok0){
                    float y0 = (acc[t][0]-mu0)*rs0*ga + ba;
                    float y1 = (acc[t][1]-mu0)*rs0*gb + bb;
                    px0[widx] = packh2(y0, y1);
                    csum[t*2]   += y0;
                    csum[t*2+1] += y1;
                }
                if (ok1){
                    float y2 = (acc[t][2]-mu1)*rs1*ga + ba;
                    float y3 = (acc[t][3]-mu1)*rs1*gb + bb;
                    px1[widx] = packh2(y2, y3);
                    csum[t*2]   += y2;
                    csum[t*2+1] += y3;
                }
            }
        }
    }

    #pragma unroll
    for (int j = 0; j < 16; j++){
        float v = csum[j];
        v += __shfl_xor_sync(0xffffffffu, v, 4);
        v += __shfl_xor_sync(0xffffffffu, v, 8);
        v += __shfl_xor_sync(0xffffffffu, v, 16);
        csum[j] = v;
    }
    if (lane < 4){
        #pragma unroll
        for (int t = 0; t < 8; t++){
            atomicAdd(&g_colsum[chalf*64 + t*8 + 2*lane],     csum[t*2]);
            atomicAdd(&g_colsum[chalf*64 + t*8 + 2*lane + 1], csum[t*2+1]);
        }
    }
}

// ================= zero per-iteration state (side stream) =================
__global__ void zero_kernel() {
    unsigned i = blockIdx.x * blockDim.x + threadIdx.x;
    unsigned stride = gridDim.x * blockDim.x;
    for (unsigned w = i; w < NWORDS; w += stride){ g_bitmap[w] = 0u; g_dup[w] = 0u; }
    if (i == 0) g_ndup = 0u;
}

__global__ void colsum0_kernel() {
    if (threadIdx.x < CC) g_colsum[threadIdx.x] = 0.f;
}

// ================= SE gate =================
__global__ void se_kernel(const float* __restrict__ w1, const float* __restrict__ b1,
                          const float* __restrict__ w2, const float* __restrict__ b2,
                          float invN)
{
    __shared__ float sq[CC];
    __shared__ float hp[4][32];
    __shared__ float h[32];
    int t = threadIdx.x;
    sq[t] = g_colsum[t] * invN;
    __syncthreads();
    int j = t & 31, grp = t >> 5;
    float a = 0.f;
    #pragma unroll 8
    for (int c = 0; c < 32; c++){
        int cc = grp*32 + c;
        a += sq[cc] * w1[cc*32 + j];
    }
    hp[grp][j] = a;
    __syncthreads();
    if (t < 32){
        float v = b1[t] + hp[0][t] + hp[1][t] + hp[2][t] + hp[3][t];
        h[t] = fmaxf(v, 0.f);
    }
    __syncthreads();
    float o = b2[t];
    #pragma unroll
    for (int jj = 0; jj < 32; jj++) o += h[jj] * w2[jj*CC + t];
    g_scale[t] = 1.f / (1.f + expf(-o));
}

// ================= bitmap + dup detection =================
__global__ void bitmap_kernel(const int* __restrict__ idx, int Nrows) {
    int i = blockIdx.x * blockDim.x + threadIdx.x;
    if (i >= Nrows) return;
    int4 v = ((const int4*)idx)[i];
    unsigned lin = (unsigned)(v.x*STRIDE_Bc + v.y*STRIDE_Tc + v.z*STRIDE_Hc + v.w);
    unsigned bit = 1u << (lin & 31);
    unsigned old = atomicOr(&g_bitmap[lin >> 5], bit);
    if (old & bit){
        unsigned dold = atomicOr(&g_dup[lin >> 5], bit);
        if (!(dold & bit)){
            unsigned pos = atomicAdd(&g_ndup, 1u);
            if (pos < NMAX) g_duplist[pos] = lin;
        }
    }
}

__global__ void scan1_kernel() {
    int b = blockIdx.x, t = threadIdx.x;
    unsigned base = b * 1024;
    unsigned s = 0;
    #pragma unroll
    for (int j = 0; j < 4; j++) s += __popc(g_bitmap[base + t*4 + j]);
    #pragma unroll
    for (int o = 16; o > 0; o >>= 1) s += __shfl_xor_sync(0xffffffffu, s, o);
    __shared__ unsigned ws[8];
    if ((t & 31) == 0) ws[t >> 5] = s;
    __syncthreads();
    if (t == 0) {
        unsigned tot = 0;
        #pragma unroll
        for (int w = 0; w < 8; w++) tot += ws[w];
        g_blocksum[b] = tot;
    }
}

__global__ void scan2_kernel() {
    int t = threadIdx.x, lane = t & 31, w = t >> 5;
    unsigned v = g_blocksum[t];
    unsigned x = v;
    #pragma unroll
    for (int o = 1; o < 32; o <<= 1) {
        unsigned n = __shfl_up_sync(0xffffffffu, x, o);
        if (lane >= o) x += n;
    }
    __shared__ unsigned ws[32];
    if (lane == 31) ws[w] = x;
    __syncthreads();
    if (w == 0) {
        unsigned y = ws[lane];
        #pragma unroll
        for (int o = 1; o < 32; o <<= 1) {
            unsigned n = __shfl_up_sync(0xffffffffu, y, o);
            if (lane >= o) y += n;
        }
        ws[lane] = y;
    }
    __syncthreads();
    unsigned incl = x + (w ? ws[w-1] : 0u);
    g_blockoff[t] = incl - v;
    if (t == 1023) g_U = incl;
}

__global__ void scan3_kernel() {
    int b = blockIdx.x, t = threadIdx.x, lane = t & 31, w = t >> 5;
    unsigned base = b * 1024;
    unsigned wd[4];
    unsigned s = 0;
    #pragma unroll
    for (int j = 0; j < 4; j++) { wd[j] = g_bitmap[base + t*4 + j]; s += __popc(wd[j]); }
    unsigned x = s;
    #pragma unroll
    for (int o = 1; o < 32; o <<= 1) {
        unsigned n = __shfl_up_sync(0xffffffffu, x, o);
        if (lane >= o) x += n;
    }
    __shared__ unsigned ws[8];
    if (lane == 31) ws[w] = x;
    __syncthreads();
    if (t == 0) {
        unsigned acc = 0;
        #pragma unroll
        for (int i = 0; i < 8; i++) { unsigned tmp = ws[i]; ws[i] = acc; acc += tmp; }
    }
    __syncthreads();
    unsigned run = ws[w] + (x - s) + g_blockoff[b];
    #pragma unroll
    for (int j = 0; j < 4; j++) {
        g_wordscan[base + t*4 + j] = run;
        run += __popc(wd[j]);
    }
}

__device__ __forceinline__ unsigned rank_of(unsigned lin){
    unsigned wo = lin >> 5, bit = lin & 31;
    return g_wordscan[wo] + __popc(g_bitmap[wo] & ((1u << bit) - 1u));
}

// ================= zero dup rows (side stream, after scans) =================
__global__ void zerodup_kernel(float* __restrict__ outM){
    int w = (blockIdx.x * blockDim.x + threadIdx.x) >> 5;
    int lane = threadIdx.x & 31;
    unsigned nd = g_ndup; if (nd > NMAX) nd = NMAX;
    int tot = gridDim.x * (blockDim.x >> 5);
    for (unsigned i = w; i < nd; i += tot){
        unsigned r = rank_of(g_duplist[i]);
        ((float4*)(outM + (size_t)r*CC))[lane] = make_float4(0.f,0.f,0.f,0.f);
    }
}

// ================= tail: rows >= U (side stream, 512 threads / 16 rows) =================
__global__ void tail_kernel(float* __restrict__ outM, float* __restrict__ outIdx,
                            float* __restrict__ outValid,
                            int hasIdx, int hasValid, int Mrows)
{
    int lane = threadIdx.x & 31, w = threadIdx.x >> 5;
    int row = blockIdx.x * 16 + w;
    unsigned U = g_U;
    if (row >= Mrows || (unsigned)row < U) return;
    stcs4(outM + (size_t)row*CC + lane*4, make_float4(0.f,0.f,0.f,0.f));
    if (lane == 0){
        if (hasValid) outValid[row] = 0.f;
        if (hasIdx) ((float4*)outIdx)[row] = make_float4(8.f, 0.f, 0.f, 0.f);
    }
}

// ================= scatter: fused relu/valid for non-dup rows (512 thr / 16 rows) =================
__global__ void scatter_kernel(const float* __restrict__ feats, const int* __restrict__ idx,
                               const uint32_t* __restrict__ X2h,
                               float* __restrict__ outM, float* __restrict__ outIdx,
                               float* __restrict__ outValid,
                               int hasIdx, int hasValid, int Nrows)
{
    int lane = threadIdx.x & 31, w = threadIdx.x >> 5;
    int row = blockIdx.x * 16 + w;
    if (row >= Nrows) return;
    int4 iv = ((const int4*)idx)[row];
    unsigned lin = (unsigned)(iv.x*STRIDE_Bc + iv.y*STRIDE_Tc + iv.z*STRIDE_Hc + iv.w);
    unsigned wo = lin >> 5, bit = lin & 31;
    unsigned r = g_wordscan[wo] + __popc(g_bitmap[wo] & ((1u << bit) - 1u));
    bool isdup = (g_dup[wo] >> bit) & 1u;

    uint2 xv = ((const uint2*)(X2h + (size_t)row*64))[lane];
    float2 v01 = unpackh2(xv.x);
    float2 v23 = unpackh2(xv.y);
    float4 f  = ((const float4*)feats)[(size_t)row*32 + lane];
    float4 sc = ((const float4*)g_scale)[lane];
    float4 o;
    o.x = v01.x*sc.x + f.x;
    o.y = v01.y*sc.y + f.y;
    o.z = v23.x*sc.z + f.z;
    o.w = v23.y*sc.w + f.w;

    if (!isdup){
        float s = fabsf(o.x) + fabsf(o.y) + fabsf(o.z) + fabsf(o.w);
        #pragma unroll
        for (int off = 16; off > 0; off >>= 1) s += __shfl_xor_sync(0xffffffffu, s, off);
        bool valid = (s > 1e-8f);
        float4 ov;
        if (valid){
            ov.x = fmaxf(o.x, 0.f); ov.y = fmaxf(o.y, 0.f);
            ov.z = fmaxf(o.z, 0.f); ov.w = fmaxf(o.w, 0.f);
        } else {
            ov = make_float4(0.f,0.f,0.f,0.f);
        }
        stcs4(outM + (size_t)r*CC + lane*4, ov);
        if (lane == 0 && hasValid) outValid[r] = valid ? 1.f : 0.f;
    } else {
        float* dst = &outM[(size_t)r*CC + lane*4];
        atomicAdd(dst+0, o.x); atomicAdd(dst+1, o.y);
        atomicAdd(dst+2, o.z); atomicAdd(dst+3, o.w);
    }
    if (hasIdx && lane == 0)
        ((float4*)outIdx)[r] = make_float4((float)iv.x, (float)iv.y, (float)iv.z, (float)iv.w);
}

// ================= finalize dup rows (relu + valid) =================
__global__ void finalizedup_kernel(float* __restrict__ outM, float* __restrict__ outValid,
                                   int hasValid){
    int w = (blockIdx.x * blockDim.x + threadIdx.x) >> 5;
    int lane = threadIdx.x & 31;
    unsigned nd = g_ndup; if (nd > NMAX) nd = NMAX;
    int tot = gridDim.x * (blockDim.x >> 5);
    for (unsigned i = w; i < nd; i += tot){
        unsigned r = rank_of(g_duplist[i]);
        float4* p = (float4*)(outM + (size_t)r*CC) + lane;
        float4 v = *p;
        float s = fabsf(v.x) + fabsf(v.y) + fabsf(v.z) + fabsf(v.w);
        #pragma unroll
        for (int off = 16; off > 0; off >>= 1) s += __shfl_xor_sync(0xffffffffu, s, off);
        bool valid = (s > 1e-8f);
        float4 ov;
        if (valid){
            ov.x = fmaxf(v.x, 0.f); ov.y = fmaxf(v.y, 0.f);
            ov.z = fmaxf(v.z, 0.f); ov.w = fmaxf(v.w, 0.f);
        } else {
            ov = make_float4(0.f,0.f,0.f,0.f);
        }
        *p = ov;
        if (lane == 0 && hasValid) outValid[r] = valid ? 1.f : 0.f;
    }
}

// ================= launch =================
extern "C" void kernel_launch(void* const* d_in, const int* in_sizes, int n_in,
                              void* d_out, int out_size)
{
    const float* feats = (const float*)d_in[0];
    const int*   indices = (const int*)d_in[1];
    const float* W1   = (const float*)d_in[2];
    const float* ln1g = (const float*)d_in[3];
    const float* ln1b = (const float*)d_in[4];
    const float* W2   = (const float*)d_in[5];
    const float* ln2g = (const float*)d_in[6];
    const float* ln2b = (const float*)d_in[7];
    const float* sew1 = (const float*)d_in[8];
    const float* seb1 = (const float*)d_in[9];
    const float* sew2 = (const float*)d_in[10];
    const float* seb2 = (const float*)d_in[11];

    int Nr = in_sizes[0] / CC;
    int M  = 2 * Nr;

    float* outM = (float*)d_out;
    long long osz = (long long)out_size;
    int hasIdx   = osz >= (long long)M * (CC + 4);
    int hasValid = osz >= (long long)M * (CC + 5);
    float* outIdx   = outM + (size_t)M * CC;
    float* outValid = outIdx + (hasIdx ? (size_t)M * 4 : 0);

    void *px2 = nullptr;
    cudaGetSymbolAddress(&px2, g_X2h);

    cudaFuncSetAttribute(fused_kernel, cudaFuncAttributeMaxDynamicSharedMemorySize, SMEM_FUSED);

    if (!(hasIdx && hasValid))
        cudaMemsetAsync(d_out, 0, (size_t)out_size * sizeof(float));

    // ---- fork side stream for the index pipeline (runs under the GEMM) ----
    cudaStream_t s2;
    cudaStreamCreateWithFlags(&s2, cudaStreamNonBlocking);
    cudaEvent_t evFork, evJoin;
    cudaEventCreateWithFlags(&evFork, cudaEventDisableTiming);
    cudaEventCreateWithFlags(&evJoin, cudaEventDisableTiming);

    cudaEventRecord(evFork, 0);
    cudaStreamWaitEvent(s2, evFork, 0);

    zero_kernel<<<2048, 256, 0, s2>>>();
    bitmap_kernel<<<(Nr + 255) / 256, 256, 0, s2>>>(indices, Nr);
    scan1_kernel<<<1024, 256, 0, s2>>>();
    scan2_kernel<<<1, 1024, 0, s2>>>();
    scan3_kernel<<<1024, 256, 0, s2>>>();
    zerodup_kernel<<<256, 256, 0, s2>>>(outM);
    tail_kernel<<<(M + 15) / 16, 512, 0, s2>>>(outM, outIdx, outValid, hasIdx, hasValid, M);
    cudaEventRecord(evJoin, s2);

    // main stream: GEMM pipeline
    colsum0_kernel<<<1, 128>>>();
    fused_kernel<<<148, 512, SMEM_FUSED>>>(feats, W1, ln1g, ln1b,
                                           W2, ln2g, ln2b, (uint32_t*)px2, Nr);
    se_kernel<<<1, CC>>>(sew1, seb1, sew2, seb2, 1.0f / (float)Nr);

    // join, then scatter + dup finalize
    cudaStreamWaitEvent(0, evJoin, 0);
    scatter_kernel<<<(Nr + 15) / 16, 512>>>(feats, indices, (const uint32_t*)px2,
                                            outM, outIdx, outValid, hasIdx, hasValid, Nr);
    finalizedup_kernel<<<256, 256>>>(outM, outValid, hasValid);
    // NOTE: stream/events intentionally not destroyed here — capture-safe.
}

// round 17
// speedup vs baseline: 1.4107x; 1.4107x over previous
#include <cuda_runtime.h>
#include <cuda_fp16.h>
#include <math.h>
#include <stdint.h>

#define CC 128
#define NMAX 300000
#define NWORDS (1u<<20)
#define STRIDE_Bc 4194304
#define STRIDE_Tc 262144
#define STRIDE_Hc 512

// ================= device scratch =================
__device__ uint32_t g_X2h[(size_t)NMAX*64];   // packed half2, [row][64]
__device__ unsigned g_bitmap[NWORDS];
__device__ unsigned g_dup[NWORDS];
__device__ unsigned g_wordscan[NWORDS];
__device__ unsigned g_blocksum[1024];
__device__ unsigned g_blockoff[1024];
__device__ unsigned g_U;
__device__ unsigned g_ndup;
__device__ unsigned g_duplist[NMAX];
__device__ float    g_colsum[CC];
__device__ float    g_scale[CC];

// ================= helpers =================
__device__ __forceinline__ uint32_t smem_u32(const void* p){
    uint32_t a;
    asm("{ .reg .u64 t; cvta.to.shared.u64 t, %1; cvt.u32.u64 %0, t; }" : "=r"(a) : "l"(p));
    return a;
}

__device__ __forceinline__ void ldsm_x4(uint32_t addr, uint32_t& r0, uint32_t& r1,
                                        uint32_t& r2, uint32_t& r3){
    asm volatile("ldmatrix.sync.aligned.m8n8.x4.shared.b16 {%0,%1,%2,%3}, [%4];"
        : "=r"(r0),"=r"(r1),"=r"(r2),"=r"(r3) : "r"(addr));
}

__device__ __forceinline__ void mma_f16(float* d, const uint32_t* a, uint32_t b0, uint32_t b1){
    asm volatile("mma.sync.aligned.m16n8k16.row.col.f32.f16.f16.f32 "
        "{%0,%1,%2,%3}, {%4,%5,%6,%7}, {%8,%9}, {%0,%1,%2,%3};"
        : "+f"(d[0]),"+f"(d[1]),"+f"(d[2]),"+f"(d[3])
        : "r"(a[0]),"r"(a[1]),"r"(a[2]),"r"(a[3]), "r"(b0),"r"(b1));
}

__device__ __forceinline__ uint32_t packh2(float a, float b){
    __half2 h = __floats2half2_rn(a, b);
    return *reinterpret_cast<uint32_t*>(&h);
}
__device__ __forceinline__ float2 unpackh2(uint32_t u){
    __half2 h = *reinterpret_cast<__half2*>(&u);
    return __half22float2(h);
}

__device__ __forceinline__ void cp_async16(uint32_t dst, const void* src, int src_bytes){
    asm volatile("cp.async.cg.shared.global [%0], [%1], 16, %2;"
        :: "r"(dst), "l"(src), "r"(src_bytes) : "memory");
}
#define CP_COMMIT() asm volatile("cp.async.commit_group;" ::: "memory")
#define CP_WAIT_ALL() asm volatile("cp.async.wait_group 0;" ::: "memory")

// streaming 16B store (evict-first; write-once outputs)
__device__ __forceinline__ void stcs4(float* p, float4 v){
    asm volatile("st.global.cs.v4.f32 [%0], {%1,%2,%3,%4};"
        :: "l"(p), "f"(v.x), "f"(v.y), "f"(v.z), "f"(v.w) : "memory");
}

// ---------------- fused-kernel SMEM layout (bytes) ----------------
#define SW        136          // W panel row stride (fp16 elements)
#define AW        68           // sA row stride (uint32 words = half2 pairs)
#define RAWSTRIDE 528          // raw fp32 row stride (132 floats, 16B aligned)
#define OFF_W1H   0
#define OFF_W2H   34816
#define OFF_SA    69632
#define OFF_RAW   104448       // 128 * 528 = 67584
#define OFF_G1    172032
#define OFF_B1    172544
#define OFF_G2    173056
#define OFF_B2    173568
#define OFF_LN    174080       // float2[128][2]
#define SMEM_FUSED 176128

// 1-pass fp16 GEMM over the staged A tile: acc[8][4] = 16 rows x 64 cols (this warp)
__device__ __forceinline__ void do_gemm(float (&acc)[8][4],
                                        const uint32_t* __restrict__ sA,
                                        uint32_t wbh,
                                        int arow0, int chalf, int belem, int rq, int q)
{
    #pragma unroll
    for (int ks = 0; ks < 8; ks++){
        uint32_t ah[4];
        const int wi0 = (arow0 + rq) * AW + ks*8 + q;
        const int wi1 = wi0 + 8*AW;
        ah[0] = sA[wi0];   ah[1] = sA[wi1];
        ah[2] = sA[wi0+4]; ah[3] = sA[wi1+4];
        #pragma unroll
        for (int np = 0; np < 4; np++){
            uint32_t boff = (uint32_t)(((chalf*64 + np*16)*SW + ks*16 + belem) * 2);
            uint32_t b0,b1,b2,b3;
            ldsm_x4(wbh + boff, b0,b1,b2,b3);
            mma_f16(acc[np*2],   ah, b0, b1);
            mma_f16(acc[np*2+1], ah, b2, b3);
        }
    }
}

// ================= fused GEMM1->LN1->ReLU->GEMM2->LN2 (cp.async pipelined) =================
__global__ __launch_bounds__(512, 1)
void fused_kernel(const float* __restrict__ A,
                  const float* __restrict__ W1, const float* __restrict__ g1v, const float* __restrict__ b1v,
                  const float* __restrict__ W2, const float* __restrict__ g2v, const float* __restrict__ b2v,
                  uint32_t* __restrict__ X2h, int Nrows)
{
    extern __shared__ char smem[];
    uint32_t sb = smem_u32(smem);
    uint32_t* sA = (uint32_t*)(smem + OFF_SA);
    float* sG1 = (float*)(smem + OFF_G1);
    float* sB1 = (float*)(smem + OFF_B1);
    float* sG2 = (float*)(smem + OFF_G2);
    float* sB2 = (float*)(smem + OFF_B2);
    float2* sLN = (float2*)(smem + OFF_LN);

    const int tid = threadIdx.x, lane = tid & 31, wid = tid >> 5;
    const int q = lane & 3, rq = lane >> 2;
    const int g = wid >> 1, chalf = wid & 1;
    const int jj = lane >> 3, rr = lane & 7;
    const int belem = ((jj >= 2 ? 8 : 0) + rr) * SW + ((jj & 1) ? 8 : 0);
    const int arow0 = g * 16;

    const int srow = tid >> 2, scolg = tid & 3;
    const uint32_t rawdst = sb + OFF_RAW + (uint32_t)(srow*RAWSTRIDE + scolg*128);
    const float* sRawRd = (const float*)(smem + OFF_RAW) + srow*132 + scolg*32;
    uint32_t* sAwr = sA + srow*AW + scolg*16;

    // ---- load W1/W2 fp16 panels ----
    {
        int n = tid & 127, kq = tid >> 7;
        __half* w1h = (__half*)(smem + OFF_W1H);
        __half* w2h = (__half*)(smem + OFF_W2H);
        #pragma unroll 4
        for (int k = kq*32; k < kq*32 + 32; k++){
            w1h[n*SW + k] = __float2half_rn(W1[k*CC + n]);
            w2h[n*SW + k] = __float2half_rn(W2[k*CC + n]);
        }
        if (tid < CC){ sG1[tid] = g1v[tid]; sB1[tid] = b1v[tid]; sG2[tid] = g2v[tid]; sB2[tid] = b2v[tid]; }
    }

    const uint32_t wb1h = sb + OFF_W1H;
    const uint32_t wb2h = sb + OFF_W2H;

    float csum[16];
    #pragma unroll
    for (int j = 0; j < 16; j++) csum[j] = 0.f;

    const int NT = (Nrows + 127) >> 7;
    const int G = gridDim.x;

    // prologue: prefetch first owned tile's raw fp32
    if (blockIdx.x < NT){
        int grow = blockIdx.x*128 + srow;
        int ok16 = (grow < Nrows) ? 16 : 0;
        const float* src = A + (size_t)grow*CC + scolg*32;
        #pragma unroll
        for (int j = 0; j < 8; j++)
            cp_async16(rawdst + j*16, src + j*4, ok16);
    }
    CP_COMMIT();
    __syncthreads();   // W panels visible

    for (int tile = blockIdx.x; tile < NT; tile += G){
        // ---- 1. wait raw tile, convert fp32->fp16 into sA ----
        CP_WAIT_ALL();
        __syncthreads();
        {
            #pragma unroll
            for (int j = 0; j < 8; j++){
                float4 v = *(const float4*)(sRawRd + j*4);
                sAwr[j*2]   = packh2(v.x, v.y);
                sAwr[j*2+1] = packh2(v.z, v.w);
            }
        }
        __syncthreads();

        // ---- 1b. prefetch next tile's raw (flies under compute) ----
        int tnext = tile + G;
        if (tnext < NT){
            int grow = tnext*128 + srow;
            int ok16 = (grow < Nrows) ? 16 : 0;
            const float* src = A + (size_t)grow*CC + scolg*32;
            #pragma unroll
            for (int j = 0; j < 8; j++)
                cp_async16(rawdst + j*16, src + j*4, ok16);
        }
        CP_COMMIT();

        const int r0 = tile*128 + g*16 + rq;
        const bool ok0 = r0 < Nrows, ok1 = (r0 + 8) < Nrows;

        // ---- 2. GEMM1 ----
        float acc[8][4];
        #pragma unroll
        for (int t = 0; t < 8; t++)
            #pragma unroll
            for (int j = 0; j < 4; j++) acc[t][j] = 0.f;
        do_gemm(acc, sA, wb1h, arow0, chalf, belem, rq, q);

        // ---- 3. LN1 stats + cross-pair exchange ----
        float s0=0.f, q0=0.f, s1=0.f, q1=0.f;
        #pragma unroll
        for (int t = 0; t < 8; t++){
            s0 += acc[t][0] + acc[t][1];
            q0 += acc[t][0]*acc[t][0] + acc[t][1]*acc[t][1];
            s1 += acc[t][2] + acc[t][3];
            q1 += acc[t][2]*acc[t][2] + acc[t][3]*acc[t][3];
        }
        #pragma unroll
        for (int o = 1; o <= 2; o <<= 1){
            s0 += __shfl_xor_sync(0xffffffffu, s0, o);
            q0 += __shfl_xor_sync(0xffffffffu, q0, o);
            s1 += __shfl_xor_sync(0xffffffffu, s1, o);
            q1 += __shfl_xor_sync(0xffffffffu, q1, o);
        }
        if (q == 0){
            sLN[(arow0 + rq)*2 + chalf]     = make_float2(s0, q0);
            sLN[(arow0 + rq + 8)*2 + chalf] = make_float2(s1, q1);
        }
        __syncthreads();
        {
            float2 p0 = sLN[(arow0 + rq)*2 + (chalf^1)];
            float2 p1 = sLN[(arow0 + rq + 8)*2 + (chalf^1)];
            float S0 = s0 + p0.x, Q0 = q0 + p0.y;
            float S1 = s1 + p1.x, Q1 = q1 + p1.y;
            float mu0 = S0*(1.f/128.f), mu1 = S1*(1.f/128.f);
            float rs0 = rsqrtf(Q0*(1.f/128.f) - mu0*mu0 + 1e-5f);
            float rs1 = rsqrtf(Q1*(1.f/128.f) - mu1*mu1 + 1e-5f);
            // ---- 4. LN1 apply + ReLU -> fp16 Y into sA ----
            #pragma unroll
            for (int t = 0; t < 8; t++){
                int c = chalf*64 + t*8 + 2*q;
                float ga = sG1[c], gb = sG1[c+1], ba = sB1[c], bb = sB1[c+1];
                float y0 = fmaxf((acc[t][0]-mu0)*rs0*ga + ba, 0.f);
                float y1 = fmaxf((acc[t][1]-mu0)*rs0*gb + bb, 0.f);
                float y2 = fmaxf((acc[t][2]-mu1)*rs1*ga + ba, 0.f);
                float y3 = fmaxf((acc[t][3]-mu1)*rs1*gb + bb, 0.f);
                int w0 = (arow0 + rq)*AW + chalf*32 + t*4 + q;
                int w1 = w0 + 8*AW;
                sA[w0] = packh2(y0, y1);
                sA[w1] = packh2(y2, y3);
            }
        }
        __syncthreads();   // Y visible

        // ---- 5. GEMM2 ----
        #pragma unroll
        for (int t = 0; t < 8; t++)
            #pragma unroll
            for (int j = 0; j < 4; j++) acc[t][j] = 0.f;
        do_gemm(acc, sA, wb2h, arow0, chalf, belem, rq, q);

        // ---- 6. LN2 stats + exchange ----
        s0=0.f; q0=0.f; s1=0.f; q1=0.f;
        #pragma unroll
        for (int t = 0; t < 8; t++){
            s0 += acc[t][0] + acc[t][1];
            q0 += acc[t][0]*acc[t][0] + acc[t][1]*acc[t][1];
            s1 += acc[t][2] + acc[t][3];
            q1 += acc[t][2]*acc[t][2] + acc[t][3]*acc[t][3];
        }
        #pragma unroll
        for (int o = 1; o <= 2; o <<= 1){
            s0 += __shfl_xor_sync(0xffffffffu, s0, o);
            q0 += __shfl_xor_sync(0xffffffffu, q0, o);
            s1 += __shfl_xor_sync(0xffffffffu, s1, o);
            q1 += __shfl_xor_sync(0xffffffffu, q1, o);
        }
        if (q == 0){
            sLN[(arow0 + rq)*2 + chalf]     = make_float2(s0, q0);
            sLN[(arow0 + rq + 8)*2 + chalf] = make_float2(s1, q1);
        }
        __syncthreads();   // all GEMM2 sA reads done -> restage safe next iter
        {
            float2 p0 = sLN[(arow0 + rq)*2 + (chalf^1)];
            float2 p1 = sLN[(arow0 + rq + 8)*2 + (chalf^1)];
            float S0 = s0 + p0.x, Q0 = q0 + p0.y;
            float S1 = s1 + p1.x, Q1 = q1 + p1.y;
            float mu0 = S0*(1.f/128.f), mu1 = S1*(1.f/128.f);
            float rs0 = rsqrtf(Q0*(1.f/128.f) - mu0*mu0 + 1e-5f);
            float rs1 = rsqrtf(Q1*(1.f/128.f) - mu1*mu1 + 1e-5f);
            uint32_t* px0 = X2h + (size_t)r0*64;
            uint32_t* px1 = px0 + 8*64;
            #pragma unroll
            for (int t = 0; t < 8; t++){
                int c = chalf*64 + t*8 + 2*q;
                int widx = chalf*32 + t*4 + q;
                float ga = sG2[c], gb = sG2[c+1], ba = sB2[c], bb = sB2[c+1];
                if (ok0){
                    float y0 = (acc[t][0]-mu0)*rs0*ga + ba;
                    float y1 = (acc[t][1]-mu0)*rs0*gb + bb;
                    px0[widx] = packh2(y0, y1);
                    csum[t*2]   += y0;
                    csum[t*2+1] += y1;
                }
                if (ok1){
                    float y2 = (acc[t][2]-mu1)*rs1*ga + ba;
                    float y3 = (acc[t][3]-mu1)*rs1*gb + bb;
                    px1[widx] = packh2(y2, y3);
                    csum[t*2]   += y2;
                    csum[t*2+1] += y3;
                }
            }
        }
    }

    #pragma unroll
    for (int j = 0; j < 16; j++){
        float v = csum[j];
        v += __shfl_xor_sync(0xffffffffu, v, 4);
        v += __shfl_xor_sync(0xffffffffu, v, 8);
        v += __shfl_xor_sync(0xffffffffu, v, 16);
        csum[j] = v;
    }
    if (lane < 4){
        #pragma unroll
        for (int t = 0; t < 8; t++){
            atomicAdd(&g_colsum[chalf*64 + t*8 + 2*lane],     csum[t*2]);
            atomicAdd(&g_colsum[chalf*64 + t*8 + 2*lane + 1], csum[t*2+1]);
        }
    }
}

// ================= zero per-iteration state (side stream) =================
__global__ void zero_kernel() {
    unsigned i = blockIdx.x * blockDim.x + threadIdx.x;
    unsigned stride = gridDim.x * blockDim.x;
    for (unsigned w = i; w < NWORDS; w += stride){ g_bitmap[w] = 0u; g_dup[w] = 0u; }
    if (i == 0) g_ndup = 0u;
}

__global__ void colsum0_kernel() {
    if (threadIdx.x < CC) g_colsum[threadIdx.x] = 0.f;
}

// ================= SE gate =================
__global__ void se_kernel(const float* __restrict__ w1, const float* __restrict__ b1,
                          const float* __restrict__ w2, const float* __restrict__ b2,
                          float invN)
{
    __shared__ float sq[CC];
    __shared__ float hp[4][32];
    __shared__ float h[32];
    int t = threadIdx.x;
    sq[t] = g_colsum[t] * invN;
    __syncthreads();
    int j = t & 31, grp = t >> 5;
    float a = 0.f;
    #pragma unroll 8
    for (int c = 0; c < 32; c++){
        int cc = grp*32 + c;
        a += sq[cc] * w1[cc*32 + j];
    }
    hp[grp][j] = a;
    __syncthreads();
    if (t < 32){
        float v = b1[t] + hp[0][t] + hp[1][t] + hp[2][t] + hp[3][t];
        h[t] = fmaxf(v, 0.f);
    }
    __syncthreads();
    float o = b2[t];
    #pragma unroll
    for (int jj = 0; jj < 32; jj++) o += h[jj] * w2[jj*CC + t];
    g_scale[t] = 1.f / (1.f + expf(-o));
}

// ================= bitmap + dup detection =================
__global__ void bitmap_kernel(const int* __restrict__ idx, int Nrows) {
    int i = blockIdx.x * blockDim.x + threadIdx.x;
    if (i >= Nrows) return;
    int4 v = ((const int4*)idx)[i];
    unsigned lin = (unsigned)(v.x*STRIDE_Bc + v.y*STRIDE_Tc + v.z*STRIDE_Hc + v.w);
    unsigned bit = 1u << (lin & 31);
    unsigned old = atomicOr(&g_bitmap[lin >> 5], bit);
    if (old & bit){
        unsigned dold = atomicOr(&g_dup[lin >> 5], bit);
        if (!(dold & bit)){
            unsigned pos = atomicAdd(&g_ndup, 1u);
            if (pos < NMAX) g_duplist[pos] = lin;
        }
    }
}

__global__ void scan1_kernel() {
    int b = blockIdx.x, t = threadIdx.x;
    unsigned base = b * 1024;
    unsigned s = 0;
    #pragma unroll
    for (int j = 0; j < 4; j++) s += __popc(g_bitmap[base + t*4 + j]);
    #pragma unroll
    for (int o = 16; o > 0; o >>= 1) s += __shfl_xor_sync(0xffffffffu, s, o);
    __shared__ unsigned ws[8];
    if ((t & 31) == 0) ws[t >> 5] = s;
    __syncthreads();
    if (t == 0) {
        unsigned tot = 0;
        #pragma unroll
        for (int w = 0; w < 8; w++) tot += ws[w];
        g_blocksum[b] = tot;
    }
}

__global__ void scan2_kernel() {
    int t = threadIdx.x, lane = t & 31, w = t >> 5;
    unsigned v = g_blocksum[t];
    unsigned x = v;
    #pragma unroll
    for (int o = 1; o < 32; o <<= 1) {
        unsigned n = __shfl_up_sync(0xffffffffu, x, o);
        if (lane >= o) x += n;
    }
    __shared__ unsigned ws[32];
    if (lane == 31) ws[w] = x;
    __syncthreads();
    if (w == 0) {
        unsigned y = ws[lane];
        #pragma unroll
        for (int o = 1; o < 32; o <<= 1) {
            unsigned n = __shfl_up_sync(0xffffffffu, y, o);
            if (lane >= o) y += n;
        }
        ws[lane] = y;
    }
    __syncthreads();
    unsigned incl = x + (w ? ws[w-1] : 0u);
    g_blockoff[t] = incl - v;
    if (t == 1023) g_U = incl;
}

__global__ void scan3_kernel() {
    int b = blockIdx.x, t = threadIdx.x, lane = t & 31, w = t >> 5;
    unsigned base = b * 1024;
    unsigned wd[4];
    unsigned s = 0;
    #pragma unroll
    for (int j = 0; j < 4; j++) { wd[j] = g_bitmap[base + t*4 + j]; s += __popc(wd[j]); }
    unsigned x = s;
    #pragma unroll
    for (int o = 1; o < 32; o <<= 1) {
        unsigned n = __shfl_up_sync(0xffffffffu, x, o);
        if (lane >= o) x += n;
    }
    __shared__ unsigned ws[8];
    if (lane == 31) ws[w] = x;
    __syncthreads();
    if (t == 0) {
        unsigned acc = 0;
        #pragma unroll
        for (int i = 0; i < 8; i++) { unsigned tmp = ws[i]; ws[i] = acc; acc += tmp; }
    }
    __syncthreads();
    unsigned run = ws[w] + (x - s) + g_blockoff[b];
    #pragma unroll
    for (int j = 0; j < 4; j++) {
        g_wordscan[base + t*4 + j] = run;
        run += __popc(wd[j]);
    }
}

__device__ __forceinline__ unsigned rank_of(unsigned lin){
    unsigned wo = lin >> 5, bit = lin & 31;
    return g_wordscan[wo] + __popc(g_bitmap[wo] & ((1u << bit) - 1u));
}

// ================= zero dup rows (side stream, after scans) =================
__global__ void zerodup_kernel(float* __restrict__ outM){
    int w = (blockIdx.x * blockDim.x + threadIdx.x) >> 5;
    int lane = threadIdx.x & 31;
    unsigned nd = g_ndup; if (nd > NMAX) nd = NMAX;
    int tot = gridDim.x * (blockDim.x >> 5);
    for (unsigned i = w; i < nd; i += tot){
        unsigned r = rank_of(g_duplist[i]);
        ((float4*)(outM + (size_t)r*CC))[lane] = make_float4(0.f,0.f,0.f,0.f);
    }
}

// ================= tail: rows >= U (side stream) =================
__global__ void tail_kernel(float* __restrict__ outM, float* __restrict__ outIdx,
                            float* __restrict__ outValid,
                            int hasIdx, int hasValid, int Mrows)
{
    int lane = threadIdx.x & 31, w = threadIdx.x >> 5;
    int row = blockIdx.x * 8 + w;
    unsigned U = g_U;
    if (row >= Mrows || (unsigned)row < U) return;
    stcs4(outM + (size_t)row*CC + lane*4, make_float4(0.f,0.f,0.f,0.f));
    if (lane == 0){
        if (hasValid) outValid[row] = 0.f;
        if (hasIdx) ((float4*)outIdx)[row] = make_float4(8.f, 0.f, 0.f, 0.f);
    }
}

// ================= scatter: fused relu/valid for non-dup rows =================
__global__ void scatter_kernel(const float* __restrict__ feats, const int* __restrict__ idx,
                               const uint32_t* __restrict__ X2h,
                               float* __restrict__ outM, float* __restrict__ outIdx,
                               float* __restrict__ outValid,
                               int hasIdx, int hasValid, int Nrows)
{
    int lane = threadIdx.x & 31, w = threadIdx.x >> 5;
    int row = blockIdx.x * 8 + w;
    if (row >= Nrows) return;
    int4 iv = ((const int4*)idx)[row];
    unsigned lin = (unsigned)(iv.x*STRIDE_Bc + iv.y*STRIDE_Tc + iv.z*STRIDE_Hc + iv.w);
    unsigned wo = lin >> 5, bit = lin & 31;
    unsigned r = g_wordscan[wo] + __popc(g_bitmap[wo] & ((1u << bit) - 1u));
    bool isdup = (g_dup[wo] >> bit) & 1u;

    uint2 xv = ((const uint2*)(X2h + (size_t)row*64))[lane];
    float2 v01 = unpackh2(xv.x);
    float2 v23 = unpackh2(xv.y);
    float4 f  = ((const float4*)feats)[(size_t)row*32 + lane];
    float4 sc = ((const float4*)g_scale)[lane];
    float4 o;
    o.x = v01.x*sc.x + f.x;
    o.y = v01.y*sc.y + f.y;
    o.z = v23.x*sc.z + f.z;
    o.w = v23.y*sc.w + f.w;

    if (!isdup){
        float s = fabsf(o.x) + fabsf(o.y) + fabsf(o.z) + fabsf(o.w);
        #pragma unroll
        for (int off = 16; off > 0; off >>= 1) s += __shfl_xor_sync(0xffffffffu, s, off);
        bool valid = (s > 1e-8f);
        float4 ov;
        if (valid){
            ov.x = fmaxf(o.x, 0.f); ov.y = fmaxf(o.y, 0.f);
            ov.z = fmaxf(o.z, 0.f); ov.w = fmaxf(o.w, 0.f);
        } else {
            ov = make_float4(0.f,0.f,0.f,0.f);
        }
        stcs4(outM + (size_t)r*CC + lane*4, ov);
        if (lane == 0 && hasValid) outValid[r] = valid ? 1.f : 0.f;
    } else {
        float* dst = &outM[(size_t)r*CC + lane*4];
        atomicAdd(dst+0, o.x); atomicAdd(dst+1, o.y);
        atomicAdd(dst+2, o.z); atomicAdd(dst+3, o.w);
    }
    if (hasIdx && lane == 0)
        ((float4*)outIdx)[r] = make_float4((float)iv.x, (float)iv.y, (float)iv.z, (float)iv.w);
}

// ================= finalize dup rows (relu + valid) =================
__global__ void finalizedup_kernel(float* __restrict__ outM, float* __restrict__ outValid,
                                   int hasValid){
    int w = (blockIdx.x * blockDim.x + threadIdx.x) >> 5;
    int lane = threadIdx.x & 31;
    unsigned nd = g_ndup; if (nd > NMAX) nd = NMAX;
    int tot = gridDim.x * (blockDim.x >> 5);
    for (unsigned i = w; i < nd; i += tot){
        unsigned r = rank_of(g_duplist[i]);
        float4* p = (float4*)(outM + (size_t)r*CC) + lane;
        float4 v = *p;
        float s = fabsf(v.x) + fabsf(v.y) + fabsf(v.z) + fabsf(v.w);
        #pragma unroll
        for (int off = 16; off > 0; off >>= 1) s += __shfl_xor_sync(0xffffffffu, s, off);
        bool valid = (s > 1e-8f);
        float4 ov;
        if (valid){
            ov.x = fmaxf(v.x, 0.f); ov.y = fmaxf(v.y, 0.f);
            ov.z = fmaxf(v.z, 0.f); ov.w = fmaxf(v.w, 0.f);
        } else {
            ov = make_float4(0.f,0.f,0.f,0.f);
        }
        *p = ov;
        if (lane == 0 && hasValid) outValid[r] = valid ? 1.f : 0.f;
    }
}

// ================= launch =================
extern "C" void kernel_launch(void* const* d_in, const int* in_sizes, int n_in,
                              void* d_out, int out_size)
{
    const float* feats = (const float*)d_in[0];
    const int*   indices = (const int*)d_in[1];
    const float* W1   = (const float*)d_in[2];
    const float* ln1g = (const float*)d_in[3];
    const float* ln1b = (const float*)d_in[4];
    const float* W2   = (const float*)d_in[5];
    const float* ln2g = (const float*)d_in[6];
    const float* ln2b = (const float*)d_in[7];
    const float* sew1 = (const float*)d_in[8];
    const float* seb1 = (const float*)d_in[9];
    const float* sew2 = (const float*)d_in[10];
    const float* seb2 = (const float*)d_in[11];

    int Nr = in_sizes[0] / CC;
    int M  = 2 * Nr;

    float* outM = (float*)d_out;
    long long osz = (long long)out_size;
    int hasIdx   = osz >= (long long)M * (CC + 4);
    int hasValid = osz >= (long long)M * (CC + 5);
    float* outIdx   = outM + (size_t)M * CC;
    float* outValid = outIdx + (hasIdx ? (size_t)M * 4 : 0);

    void *px2 = nullptr;
    cudaGetSymbolAddress(&px2, g_X2h);

    cudaFuncSetAttribute(fused_kernel, cudaFuncAttributeMaxDynamicSharedMemorySize, SMEM_FUSED);

    if (!(hasIdx && hasValid))
        cudaMemsetAsync(d_out, 0, (size_t)out_size * sizeof(float));

    // ---- fork side stream for the index pipeline (runs under the GEMM) ----
    cudaStream_t s2;
    cudaStreamCreateWithFlags(&s2, cudaStreamNonBlocking);
    cudaEvent_t evFork, evJoin;
    cudaEventCreateWithFlags(&evFork, cudaEventDisableTiming);
    cudaEventCreateWithFlags(&evJoin, cudaEventDisableTiming);

    cudaEventRecord(evFork, 0);
    cudaStreamWaitEvent(s2, evFork, 0);

    zero_kernel<<<2048, 256, 0, s2>>>();
    bitmap_kernel<<<(Nr + 255) / 256, 256, 0, s2>>>(indices, Nr);
    scan1_kernel<<<1024, 256, 0, s2>>>();
    scan2_kernel<<<1, 1024, 0, s2>>>();
    scan3_kernel<<<1024, 256, 0, s2>>>();
    zerodup_kernel<<<256, 256, 0, s2>>>(outM);
    tail_kernel<<<(M + 7) / 8, 256, 0, s2>>>(outM, outIdx, outValid, hasIdx, hasValid, M);
    cudaEventRecord(evJoin, s2);

    // main stream: GEMM pipeline
    colsum0_kernel<<<1, 128>>>();
    fused_kernel<<<148, 512, SMEM_FUSED>>>(feats, W1, ln1g, ln1b,
                                           W2, ln2g, ln2b, (uint32_t*)px2, Nr);
    se_kernel<<<1, CC>>>(sew1, seb1, sew2, seb2, 1.0f / (float)Nr);

    // join, then scatter + dup finalize
    cudaStreamWaitEvent(0, evJoin, 0);
    scatter_kernel<<<(Nr + 7) / 8, 256>>>(feats, indices, (const uint32_t*)px2,
                                          outM, outIdx, outValid, hasIdx, hasValid, Nr);
    finalizedup_kernel<<<256, 256>>>(outM, outValid, hasValid);
    // NOTE: stream/events intentionally not destroyed here — capture-safe.
}